// round 3
// baseline (speedup 1.0000x reference)
#include <cuda_runtime.h>
#include <cstddef>

#define N_MAX 50000
#define E_MAX 800000
#define FIN   256
#define FOUT  128

// ---------------------------------------------------------------------------
// Scratch (static device globals — no runtime allocation allowed)
// ---------------------------------------------------------------------------
__device__ float g_m[(size_t)N_MAX * FOUT];   // mean message  m = relu(xWm)*att*n1[src]
__device__ float g_v[(size_t)N_MAX * FOUT];   // var  message  v = relu(xWv)*att^2*n1[src]^2
__device__ int   g_cnt[N_MAX];                // in-degree histogram
__device__ int   g_off[N_MAX + 1];            // CSR row offsets (by dst)
__device__ int   g_cur[N_MAX];                // scatter cursors
__device__ int   g_ssrc[E_MAX];               // src ids sorted by dst
__device__ float g_norm1[N_MAX];

// ---------------------------------------------------------------------------
// Degree histogram
// ---------------------------------------------------------------------------
__global__ void deg_kernel(const int* __restrict__ dst, int E) {
    for (int i = blockIdx.x * blockDim.x + threadIdx.x; i < E;
         i += gridDim.x * blockDim.x)
        atomicAdd(&g_cnt[dst[i]], 1);
}

// ---------------------------------------------------------------------------
// Single-block scan: exclusive prefix sum of g_cnt -> g_off/g_cur,
// fused with norm1 = rsqrt(max(deg,1)).
// ---------------------------------------------------------------------------
__global__ void scan_kernel(int n, int E) {
    __shared__ int part[1024];
    const int t = threadIdx.x;
    const int chunk = (n + 1023) / 1024;
    const int beg = t * chunk;
    const int end = (beg + chunk < n) ? beg + chunk : n;

    int s = 0;
    for (int i = beg; i < end; i++) s += g_cnt[i];
    part[t] = s;
    __syncthreads();

    // Hillis-Steele inclusive scan over 1024 partials
    for (int off = 1; off < 1024; off <<= 1) {
        int tmp = (t >= off) ? part[t - off] : 0;
        __syncthreads();
        part[t] += tmp;
        __syncthreads();
    }

    int run = part[t] - s;   // exclusive base for this thread's chunk
    for (int i = beg; i < end; i++) {
        g_off[i] = run;
        g_cur[i] = run;
        int c = g_cnt[i];
        run += c;
        float d = (float)((c < 1) ? 1 : c);
        g_norm1[i] = rsqrtf(d);
    }
    if (t == 1023) g_off[n] = E;
}

// ---------------------------------------------------------------------------
// Counting-sort scatter: place each edge's src into its dst segment.
// ---------------------------------------------------------------------------
__global__ void scatter_kernel(const int* __restrict__ src,
                               const int* __restrict__ dst, int E) {
    for (int i = blockIdx.x * blockDim.x + threadIdx.x; i < E;
         i += gridDim.x * blockDim.x) {
        int d = dst[i];
        int pos = atomicAdd(&g_cur[d], 1);
        g_ssrc[pos] = src[i];
    }
}

// ---------------------------------------------------------------------------
// Fused dual-GEMM + message epilogue (unchanged from R2).
// C tile: 64 rows x 128 cols, 4x8x2 microtile per thread.
// ---------------------------------------------------------------------------
__global__ void __launch_bounds__(256, 2) gemm_msg_kernel(
    const float* __restrict__ feat,
    const float* __restrict__ Wm,
    const float* __restrict__ Wv,
    int n)
{
    __shared__ float sA[16][64];      // feat tile, stored [k][m]
    __shared__ float sWm[16][FOUT];   // [k][n]
    __shared__ float sWv[16][FOUT];

    const int t  = threadIdx.x;
    const int m0 = blockIdx.x * 64;
    const int tm = t >> 4;
    const int tn = t & 15;

    float accM[4][8];
    float accV[4][8];
#pragma unroll
    for (int i = 0; i < 4; i++)
#pragma unroll
        for (int j = 0; j < 8; j++) { accM[i][j] = 0.0f; accV[i][j] = 0.0f; }

    const int  arow = t >> 2;
    const int  ac4  = (t & 3) * 4;
    const int  wr   = t >> 5;
    const int  wc   = (t & 31) * 4;
    const bool aok  = (m0 + arow) < n;
    const float* aptr = feat + (size_t)(m0 + arow) * FIN + ac4;

    for (int kb = 0; kb < FIN; kb += 16) {
        float4 av = make_float4(0.0f, 0.0f, 0.0f, 0.0f);
        if (aok) av = *(const float4*)(aptr + kb);
        sA[ac4 + 0][arow] = av.x;
        sA[ac4 + 1][arow] = av.y;
        sA[ac4 + 2][arow] = av.z;
        sA[ac4 + 3][arow] = av.w;

        *(float4*)&sWm[wr][wc]     = *(const float4*)(Wm + (size_t)(kb + wr)     * FOUT + wc);
        *(float4*)&sWm[wr + 8][wc] = *(const float4*)(Wm + (size_t)(kb + wr + 8) * FOUT + wc);
        *(float4*)&sWv[wr][wc]     = *(const float4*)(Wv + (size_t)(kb + wr)     * FOUT + wc);
        *(float4*)&sWv[wr + 8][wc] = *(const float4*)(Wv + (size_t)(kb + wr + 8) * FOUT + wc);

        __syncthreads();

#pragma unroll
        for (int k = 0; k < 16; k++) {
            float4 a4 = *(const float4*)&sA[k][tm * 4];
            float4 b0 = *(const float4*)&sWm[k][tn * 8];
            float4 b1 = *(const float4*)&sWm[k][tn * 8 + 4];
            float4 c0 = *(const float4*)&sWv[k][tn * 8];
            float4 c1 = *(const float4*)&sWv[k][tn * 8 + 4];
            float aa[4] = {a4.x, a4.y, a4.z, a4.w};
            float bb[8] = {b0.x, b0.y, b0.z, b0.w, b1.x, b1.y, b1.z, b1.w};
            float cc[8] = {c0.x, c0.y, c0.z, c0.w, c1.x, c1.y, c1.z, c1.w};
#pragma unroll
            for (int i = 0; i < 4; i++)
#pragma unroll
                for (int j = 0; j < 8; j++) {
                    accM[i][j] = fmaf(aa[i], bb[j], accM[i][j]);
                    accV[i][j] = fmaf(aa[i], cc[j], accV[i][j]);
                }
        }
        __syncthreads();
    }

#pragma unroll
    for (int i = 0; i < 4; i++) {
        int node = m0 + tm * 4 + i;
        if (node >= n) continue;
        float n1 = g_norm1[node];
        float n2 = n1 * n1;
        float mo[8], vo[8];
#pragma unroll
        for (int j = 0; j < 8; j++) {
            float mean = fmaxf(accM[i][j], 0.0f);
            float var  = fmaxf(accV[i][j], 0.0f);
            float att  = __expf(-var);          // GAMMA = 1.0
            mo[j] = mean * att * n1;
            vo[j] = var * att * att * n2;
        }
        float* pm = g_m + (size_t)node * FOUT + tn * 8;
        float* pv = g_v + (size_t)node * FOUT + tn * 8;
        *(float4*)(pm)     = make_float4(mo[0], mo[1], mo[2], mo[3]);
        *(float4*)(pm + 4) = make_float4(mo[4], mo[5], mo[6], mo[7]);
        *(float4*)(pv)     = make_float4(vo[0], vo[1], vo[2], vo[3]);
        *(float4*)(pv + 4) = make_float4(vo[4], vo[5], vo[6], vo[7]);
    }
}

// ---------------------------------------------------------------------------
// CSR aggregation: one warp per dst node. Each lane owns one float4 column
// slice of both mean and var rows, accumulates over the node's edge segment,
// and writes the output exactly once with dst-norm fused (no atomics, no
// output memset, no separate scale pass).
// ---------------------------------------------------------------------------
__global__ void agg_csr_kernel(float* __restrict__ out_mean,
                               float* __restrict__ out_var,
                               int n)
{
    int w    = (int)((blockIdx.x * (size_t)blockDim.x + threadIdx.x) >> 5);
    int lane = threadIdx.x & 31;
    if (w >= n) return;

    int b = g_off[w];
    int e = g_off[w + 1];

    float4 am = make_float4(0.0f, 0.0f, 0.0f, 0.0f);
    float4 av = make_float4(0.0f, 0.0f, 0.0f, 0.0f);

    int i = b;
    // 2-way unrolled for memory-level parallelism
    for (; i + 2 <= e; i += 2) {
        int s0 = __ldg(g_ssrc + i);
        int s1 = __ldg(g_ssrc + i + 1);
        const float4 m0 = *(const float4*)(g_m + (size_t)s0 * FOUT + lane * 4);
        const float4 v0 = *(const float4*)(g_v + (size_t)s0 * FOUT + lane * 4);
        const float4 m1 = *(const float4*)(g_m + (size_t)s1 * FOUT + lane * 4);
        const float4 v1 = *(const float4*)(g_v + (size_t)s1 * FOUT + lane * 4);
        am.x += m0.x + m1.x; am.y += m0.y + m1.y;
        am.z += m0.z + m1.z; am.w += m0.w + m1.w;
        av.x += v0.x + v1.x; av.y += v0.y + v1.y;
        av.z += v0.z + v1.z; av.w += v0.w + v1.w;
    }
    if (i < e) {
        int s0 = __ldg(g_ssrc + i);
        const float4 m0 = *(const float4*)(g_m + (size_t)s0 * FOUT + lane * 4);
        const float4 v0 = *(const float4*)(g_v + (size_t)s0 * FOUT + lane * 4);
        am.x += m0.x; am.y += m0.y; am.z += m0.z; am.w += m0.w;
        av.x += v0.x; av.y += v0.y; av.z += v0.z; av.w += v0.w;
    }

    float n1 = g_norm1[w];
    float n2 = n1 * n1;
    am.x *= n1; am.y *= n1; am.z *= n1; am.w *= n1;
    av.x *= n2; av.y *= n2; av.z *= n2; av.w *= n2;

    *(float4*)(out_mean + (size_t)w * FOUT + lane * 4) = am;
    *(float4*)(out_var  + (size_t)w * FOUT + lane * 4) = av;
}

// ---------------------------------------------------------------------------
// Launch
// ---------------------------------------------------------------------------
extern "C" void kernel_launch(void* const* d_in, const int* in_sizes, int n_in,
                              void* d_out, int out_size)
{
    const float* feat = (const float*)d_in[0];
    const int*   esrc = (const int*)d_in[1];
    const int*   edst = (const int*)d_in[2];
    const float* Wm   = (const float*)d_in[3];
    const float* Wv   = (const float*)d_in[4];
    float* out = (float*)d_out;

    int n = in_sizes[0] / FIN;   // 50000
    int E = in_sizes[1];         // 800000

    float* out_mean = out;
    float* out_var  = out + (size_t)n * FOUT;

    void* cnt_ptr = nullptr;
    cudaGetSymbolAddress(&cnt_ptr, g_cnt);
    cudaMemsetAsync(cnt_ptr, 0, (size_t)N_MAX * sizeof(int));

    deg_kernel<<<592, 256>>>(edst, E);
    scan_kernel<<<1, 1024>>>(n, E);
    scatter_kernel<<<592, 256>>>(esrc, edst, E);

    gemm_msg_kernel<<<(n + 63) / 64, 256>>>(feat, Wm, Wv, n);

    // one warp per node
    int warps_per_block = 256 / 32;
    int agg_blocks = (n + warps_per_block - 1) / warps_per_block;
    agg_csr_kernel<<<agg_blocks, 256>>>(out_mean, out_var, n);
}

// round 4
// speedup vs baseline: 1.1704x; 1.1704x over previous
#include <cuda_runtime.h>
#include <cstddef>

#define N_MAX 50000
#define E_MAX 800000
#define FIN   256
#define FOUT  128

// ---------------------------------------------------------------------------
// Scratch (static device globals — no runtime allocation allowed)
// ---------------------------------------------------------------------------
__device__ float g_m[(size_t)N_MAX * FOUT];   // mean message  m = relu(xWm)*att*n1[src]
__device__ float g_v[(size_t)N_MAX * FOUT];   // var  message  v = relu(xWv)*att^2*n1[src]^2
__device__ int   g_cnt[N_MAX];                // in-degree histogram
__device__ int   g_off[N_MAX + 1];            // CSR row offsets (by dst)
__device__ int   g_cur[N_MAX];                // scatter cursors
__device__ int   g_ssrc[E_MAX];               // src ids sorted by dst
__device__ float g_norm1[N_MAX];

// ---------------------------------------------------------------------------
// Degree histogram
// ---------------------------------------------------------------------------
__global__ void deg_kernel(const int* __restrict__ dst, int E) {
    for (int i = blockIdx.x * blockDim.x + threadIdx.x; i < E;
         i += gridDim.x * blockDim.x)
        atomicAdd(&g_cnt[dst[i]], 1);
}

// ---------------------------------------------------------------------------
// Single-block scan: exclusive prefix sum of g_cnt -> g_off/g_cur,
// fused with norm1 = rsqrt(max(deg,1)).
// ---------------------------------------------------------------------------
__global__ void scan_kernel(int n, int E) {
    __shared__ int part[1024];
    const int t = threadIdx.x;
    const int chunk = (n + 1023) / 1024;
    const int beg = t * chunk;
    const int end = (beg + chunk < n) ? beg + chunk : n;

    int s = 0;
    for (int i = beg; i < end; i++) s += g_cnt[i];
    part[t] = s;
    __syncthreads();

    for (int off = 1; off < 1024; off <<= 1) {
        int tmp = (t >= off) ? part[t - off] : 0;
        __syncthreads();
        part[t] += tmp;
        __syncthreads();
    }

    int run = part[t] - s;   // exclusive base for this thread's chunk
    for (int i = beg; i < end; i++) {
        g_off[i] = run;
        g_cur[i] = run;
        int c = g_cnt[i];
        run += c;
        float d = (float)((c < 1) ? 1 : c);
        g_norm1[i] = rsqrtf(d);
    }
    if (t == 1023) g_off[n] = E;
}

// ---------------------------------------------------------------------------
// Counting-sort scatter: place each edge's src into its dst segment.
// ---------------------------------------------------------------------------
__global__ void scatter_kernel(const int* __restrict__ src,
                               const int* __restrict__ dst, int E) {
    for (int i = blockIdx.x * blockDim.x + threadIdx.x; i < E;
         i += gridDim.x * blockDim.x) {
        int d = dst[i];
        int pos = atomicAdd(&g_cur[d], 1);
        g_ssrc[pos] = src[i];
    }
}

// ---------------------------------------------------------------------------
// Fused dual-GEMM + message epilogue, v2: 128x128 block tile, 256 threads,
// 8x8 microtile per thread per matrix (split-column: {tn*4, 64+tn*4} /
// {tm*4, 64+tm*4}) -> 0.75 B LDS per FMA, conflict-free LDS.128.
// ---------------------------------------------------------------------------
__global__ void __launch_bounds__(256) gemm_msg_kernel(
    const float* __restrict__ feat,
    const float* __restrict__ Wm,
    const float* __restrict__ Wv,
    int n)
{
    __shared__ float sA[16][128];     // feat tile, stored [k][m]
    __shared__ float sWm[16][128];    // [k][n]
    __shared__ float sWv[16][128];

    const int t  = threadIdx.x;
    const int m0 = blockIdx.x * 128;
    const int tm = t >> 4;            // 0..15
    const int tn = t & 15;            // 0..15

    // accX[mi][nj][r] is a float4 over the 4 n-components
    float4 accM[2][2][4];
    float4 accV[2][2][4];
#pragma unroll
    for (int mi = 0; mi < 2; mi++)
#pragma unroll
        for (int nj = 0; nj < 2; nj++)
#pragma unroll
            for (int r = 0; r < 4; r++) {
                accM[mi][nj][r] = make_float4(0.f, 0.f, 0.f, 0.f);
                accV[mi][nj][r] = make_float4(0.f, 0.f, 0.f, 0.f);
            }

    // A-loader mapping: each thread loads 2 float4 of feat
    const int  arow  = t & 127;              // 0..127
    const int  ak4   = (t >> 7) * 4;         // 0 or 4 (second load at +8)
    const bool aok   = (m0 + arow) < n;
    const float* aptr = feat + (size_t)(m0 + arow) * FIN;

    // W-loader mapping: thread handles k-row (t>>4), cols (t&15)*4 and +64
    const int wr = t >> 4;                   // 0..15
    const int wc = (t & 15) * 4;             // 0..60

    for (int kb = 0; kb < FIN; kb += 16) {
        float4 a0 = make_float4(0.f, 0.f, 0.f, 0.f);
        float4 a1 = make_float4(0.f, 0.f, 0.f, 0.f);
        if (aok) {
            a0 = *(const float4*)(aptr + kb + ak4);
            a1 = *(const float4*)(aptr + kb + ak4 + 8);
        }
        sA[ak4 + 0][arow] = a0.x;
        sA[ak4 + 1][arow] = a0.y;
        sA[ak4 + 2][arow] = a0.z;
        sA[ak4 + 3][arow] = a0.w;
        sA[ak4 + 8][arow] = a1.x;
        sA[ak4 + 9][arow] = a1.y;
        sA[ak4 + 10][arow] = a1.z;
        sA[ak4 + 11][arow] = a1.w;

        *(float4*)&sWm[wr][wc]      = *(const float4*)(Wm + (size_t)(kb + wr) * FOUT + wc);
        *(float4*)&sWm[wr][wc + 64] = *(const float4*)(Wm + (size_t)(kb + wr) * FOUT + wc + 64);
        *(float4*)&sWv[wr][wc]      = *(const float4*)(Wv + (size_t)(kb + wr) * FOUT + wc);
        *(float4*)&sWv[wr][wc + 64] = *(const float4*)(Wv + (size_t)(kb + wr) * FOUT + wc + 64);

        __syncthreads();

#pragma unroll
        for (int k = 0; k < 16; k++) {
            float4 av0 = *(const float4*)&sA[k][tm * 4];
            float4 av1 = *(const float4*)&sA[k][64 + tm * 4];
            float4 bm0 = *(const float4*)&sWm[k][tn * 4];
            float4 bm1 = *(const float4*)&sWm[k][64 + tn * 4];
            float4 bv0 = *(const float4*)&sWv[k][tn * 4];
            float4 bv1 = *(const float4*)&sWv[k][64 + tn * 4];

            float am[2][4] = {{av0.x, av0.y, av0.z, av0.w},
                              {av1.x, av1.y, av1.z, av1.w}};
            float4 bm[2] = {bm0, bm1};
            float4 bv[2] = {bv0, bv1};

#pragma unroll
            for (int mi = 0; mi < 2; mi++)
#pragma unroll
                for (int r = 0; r < 4; r++) {
                    float a = am[mi][r];
#pragma unroll
                    for (int nj = 0; nj < 2; nj++) {
                        accM[mi][nj][r].x = fmaf(a, bm[nj].x, accM[mi][nj][r].x);
                        accM[mi][nj][r].y = fmaf(a, bm[nj].y, accM[mi][nj][r].y);
                        accM[mi][nj][r].z = fmaf(a, bm[nj].z, accM[mi][nj][r].z);
                        accM[mi][nj][r].w = fmaf(a, bm[nj].w, accM[mi][nj][r].w);
                        accV[mi][nj][r].x = fmaf(a, bv[nj].x, accV[mi][nj][r].x);
                        accV[mi][nj][r].y = fmaf(a, bv[nj].y, accV[mi][nj][r].y);
                        accV[mi][nj][r].z = fmaf(a, bv[nj].z, accV[mi][nj][r].z);
                        accV[mi][nj][r].w = fmaf(a, bv[nj].w, accV[mi][nj][r].w);
                    }
                }
        }
        __syncthreads();
    }

    // Epilogue: relu, attention, src-side norm -> per-node messages
#pragma unroll
    for (int mi = 0; mi < 2; mi++)
#pragma unroll
        for (int r = 0; r < 4; r++) {
            int node = m0 + mi * 64 + tm * 4 + r;
            if (node >= n) continue;
            float n1 = g_norm1[node];
            float n2 = n1 * n1;
#pragma unroll
            for (int nj = 0; nj < 2; nj++) {
                float4 M = accM[mi][nj][r];
                float4 V = accV[mi][nj][r];
                float4 mo, vo;
                {
                    float mean = fmaxf(M.x, 0.f), var = fmaxf(V.x, 0.f);
                    float att = __expf(-var);
                    mo.x = mean * att * n1; vo.x = var * att * att * n2;
                }
                {
                    float mean = fmaxf(M.y, 0.f), var = fmaxf(V.y, 0.f);
                    float att = __expf(-var);
                    mo.y = mean * att * n1; vo.y = var * att * att * n2;
                }
                {
                    float mean = fmaxf(M.z, 0.f), var = fmaxf(V.z, 0.f);
                    float att = __expf(-var);
                    mo.z = mean * att * n1; vo.z = var * att * att * n2;
                }
                {
                    float mean = fmaxf(M.w, 0.f), var = fmaxf(V.w, 0.f);
                    float att = __expf(-var);
                    mo.w = mean * att * n1; vo.w = var * att * att * n2;
                }
                int col = nj * 64 + tn * 4;
                *(float4*)(g_m + (size_t)node * FOUT + col) = mo;
                *(float4*)(g_v + (size_t)node * FOUT + col) = vo;
            }
        }
}

// ---------------------------------------------------------------------------
// CSR aggregation: one warp per dst node (unchanged from R3).
// ---------------------------------------------------------------------------
__global__ void agg_csr_kernel(float* __restrict__ out_mean,
                               float* __restrict__ out_var,
                               int n)
{
    int w    = (int)((blockIdx.x * (size_t)blockDim.x + threadIdx.x) >> 5);
    int lane = threadIdx.x & 31;
    if (w >= n) return;

    int b = g_off[w];
    int e = g_off[w + 1];

    float4 am = make_float4(0.0f, 0.0f, 0.0f, 0.0f);
    float4 av = make_float4(0.0f, 0.0f, 0.0f, 0.0f);

    int i = b;
    for (; i + 2 <= e; i += 2) {
        int s0 = __ldg(g_ssrc + i);
        int s1 = __ldg(g_ssrc + i + 1);
        const float4 m0 = *(const float4*)(g_m + (size_t)s0 * FOUT + lane * 4);
        const float4 v0 = *(const float4*)(g_v + (size_t)s0 * FOUT + lane * 4);
        const float4 m1 = *(const float4*)(g_m + (size_t)s1 * FOUT + lane * 4);
        const float4 v1 = *(const float4*)(g_v + (size_t)s1 * FOUT + lane * 4);
        am.x += m0.x + m1.x; am.y += m0.y + m1.y;
        am.z += m0.z + m1.z; am.w += m0.w + m1.w;
        av.x += v0.x + v1.x; av.y += v0.y + v1.y;
        av.z += v0.z + v1.z; av.w += v0.w + v1.w;
    }
    if (i < e) {
        int s0 = __ldg(g_ssrc + i);
        const float4 m0 = *(const float4*)(g_m + (size_t)s0 * FOUT + lane * 4);
        const float4 v0 = *(const float4*)(g_v + (size_t)s0 * FOUT + lane * 4);
        am.x += m0.x; am.y += m0.y; am.z += m0.z; am.w += m0.w;
        av.x += v0.x; av.y += v0.y; av.z += v0.z; av.w += v0.w;
    }

    float n1 = g_norm1[w];
    float n2 = n1 * n1;
    am.x *= n1; am.y *= n1; am.z *= n1; am.w *= n1;
    av.x *= n2; av.y *= n2; av.z *= n2; av.w *= n2;

    *(float4*)(out_mean + (size_t)w * FOUT + lane * 4) = am;
    *(float4*)(out_var  + (size_t)w * FOUT + lane * 4) = av;
}

// ---------------------------------------------------------------------------
// Launch
// ---------------------------------------------------------------------------
extern "C" void kernel_launch(void* const* d_in, const int* in_sizes, int n_in,
                              void* d_out, int out_size)
{
    const float* feat = (const float*)d_in[0];
    const int*   esrc = (const int*)d_in[1];
    const int*   edst = (const int*)d_in[2];
    const float* Wm   = (const float*)d_in[3];
    const float* Wv   = (const float*)d_in[4];
    float* out = (float*)d_out;

    int n = in_sizes[0] / FIN;   // 50000
    int E = in_sizes[1];         // 800000

    float* out_mean = out;
    float* out_var  = out + (size_t)n * FOUT;

    void* cnt_ptr = nullptr;
    cudaGetSymbolAddress(&cnt_ptr, g_cnt);
    cudaMemsetAsync(cnt_ptr, 0, (size_t)N_MAX * sizeof(int));

    deg_kernel<<<592, 256>>>(edst, E);
    scan_kernel<<<1, 1024>>>(n, E);
    scatter_kernel<<<592, 256>>>(esrc, edst, E);

    gemm_msg_kernel<<<(n + 127) / 128, 256>>>(feat, Wm, Wv, n);

    int warps_per_block = 256 / 32;
    int agg_blocks = (n + warps_per_block - 1) / warps_per_block;
    agg_csr_kernel<<<agg_blocks, 256>>>(out_mean, out_var, n);
}